// round 16
// baseline (speedup 1.0000x reference)
#include <cuda_runtime.h>
#include <cstdint>

typedef unsigned long long ull;

#define NB      16
#define NENT    100000
#define NTILES  3125           // NENT / 32
#define NSTAT   2960           // 1480 pairs * 2 static tiles
#define GRID    296            // 2 blocks per SM (148 SMs)
#define TPB     320            // 10 warps = 5 pairs
#define NW      10
#define NPAIR   5
#define ROWF4   33             // float4 per staged row (32 data + 1 pad -> conflict-free)
#define PAIR_F4 (32 * ROWF4)   // 1056 float4 per pair tile
// dynamic smem: h 8192 B + 5 pairs * 16896 B = 92672 B
#define SMEM_BYTES (8192 + NPAIR * PAIR_F4 * 16)

// ---------------- device scratch (allocation-free) ----------------
__device__ float    g_part[NB * GRID];
__device__ unsigned g_qctr;    // remainder-tile work queue (resets to 0 each replay)
__device__ unsigned g_done;    // grid barrier epoch counter (monotonic)

// ---------------- packed f32x2 helpers (sm_103a) ----------------
__device__ __forceinline__ ull add2(ull a, ull b) {
    ull r; asm("add.rn.f32x2 %0,%1,%2;" : "=l"(r) : "l"(a), "l"(b)); return r;
}
__device__ __forceinline__ ull mul2(ull a, ull b) {
    ull r; asm("mul.rn.f32x2 %0,%1,%2;" : "=l"(r) : "l"(a), "l"(b)); return r;
}
__device__ __forceinline__ ull fma2(ull a, ull b, ull c) {
    ull r; asm("fma.rn.f32x2 %0,%1,%2,%3;" : "=l"(r) : "l"(a), "l"(b), "l"(c)); return r;
}
__device__ __forceinline__ ull abs2(ull a) { return a & 0x7FFFFFFF7FFFFFFFull; }
__device__ __forceinline__ ull pk2(float a, float b) {
    ull r; asm("mov.b64 %0,{%1,%2};" : "=l"(r) : "f"(a), "f"(b)); return r;
}
__device__ __forceinline__ float2 upk(ull a) {
    float2 f; asm("mov.b64 {%0,%1},%2;" : "=f"(f.x), "=f"(f.y) : "l"(a)); return f;
}
__device__ __forceinline__ float wsum(float v) {
    #pragma unroll
    for (int o = 16; o; o >>= 1) v += __shfl_xor_sync(0xffffffffu, v, o);
    return v;
}
__device__ __forceinline__ unsigned sm_u32(const void* p) {
    unsigned a;
    asm("{ .reg .u64 t; cvta.to.shared.u64 t, %1; cvt.u32.u64 %0, t; }" : "=r"(a) : "l"(p));
    return a;
}
__device__ __forceinline__ void cpa16(unsigned dst, const void* src) {
    asm volatile("cp.async.cg.shared.global [%0], [%1], 16;" :: "r"(dst), "l"(src));
}
__device__ __forceinline__ void barp(int id) {   // pair barrier: 64 threads
    asm volatile("bar.sync %0, 64;" :: "r"(id) : "memory");
}

// =============== single fused kernel ===============
__global__ void __launch_bounds__(TPB, 2)
k_fused(const float* __restrict__ ent, const float* __restrict__ relemb,
        const int* __restrict__ e1w, const int* __restrict__ relw,
        float* __restrict__ out) {
    extern __shared__ float smf[];
    float*      hs  = smf;                             // 16*128 floats, persistent
    ulonglong2* hs2 = (ulonglong2*)smf;                // [16][32] 16B chunks

    int tid = threadIdx.x, w = tid >> 5, l = tid & 31;
    int p = w >> 1, role = w & 1;                      // pair id, b-half role

    float4*     xs4  = (float4*)(smf + 2048) + p * PAIR_F4;
    unsigned    xw_u = sm_u32(xs4);
    const ulonglong2* myrow2 = (const ulonglong2*)(xs4 + l * ROWF4);  // 32 chunks/row

    __shared__ unsigned tsl[NPAIR];
    __shared__ float    sp[NW][8];
    __shared__ float    sinv_s[NB];

    // ---- index width detection (int64 => high words zero) ----
    int odd  = e1w[1] | e1w[3] | e1w[5] | e1w[7] | e1w[9] | e1w[11] | e1w[13] | e1w[15];
    int is64 = (odd == 0);

    // ---- build h = norm(ent[e1[b]]) + norm(rel[rel[b]]) ----
    for (int b = w; b < NB; b += NW) {
        long long ei, ri;
        if (is64) { ei = ((const long long*)e1w)[b]; ri = ((const long long*)relw)[b]; }
        else      { ei = (long long)e1w[b];          ri = (long long)relw[b]; }
        float4 a = ((const float4*)ent)[(size_t)ei * 32 + l];
        float sa = wsum(fmaf(a.x, a.x, fmaf(a.y, a.y, fmaf(a.z, a.z, a.w * a.w))));
        float ia = rsqrtf(fmaxf(sa, 1e-24f));
        float4 c = ((const float4*)relemb)[(size_t)ri * 32 + l];
        float sc = wsum(fmaf(c.x, c.x, fmaf(c.y, c.y, fmaf(c.z, c.z, c.w * c.w))));
        float ic = rsqrtf(fmaxf(sc, 1e-24f));
        float4 h;
        h.x = fmaf(a.x, ia, c.x * ic);
        h.y = fmaf(a.y, ia, c.y * ic);
        h.z = fmaf(a.z, ia, c.z * ic);
        h.w = fmaf(a.w, ia, c.w * ic);
        ((float4*)hs)[b * 32 + l] = h;
    }
    __syncthreads();

    float es[8];
    #pragma unroll
    for (int j = 0; j < 8; j++) es[j] = 0.0f;
    const int bq  = role * 8;                          // my b rows: bq..bq+7
    const int bid = p + 1;                             // named barrier id
    const ulonglong2* hb = hs2 + bq * 32;

    // ---- static first tile: no atomic, no communication ----
    const unsigned gp = (unsigned)blockIdx.x * NPAIR + (unsigned)p;  // 0..1479
    unsigned t = 2u * gp;                              // always < NSTAT

    // =============== phase 1: dist -> exp -> store ===============
    while (t < (unsigned)NTILES) {
        int base = (int)t * 32;
        bool first = (t == 2u * gp);

        // stage my role's 16 rows (coalesced 512B rows; lane l copies 16B chunk l)
        {
            const char* src = (const char*)ent + ((size_t)base + role * 16) * 512 + l * 16;
            unsigned    dst = xw_u + (unsigned)((role * 16) * ROWF4 + l) * 16;
            #pragma unroll
            for (int k = 0; k < 16; k++)
                cpa16(dst + k * (ROWF4 * 16), src + (size_t)k * 512);
            asm volatile("cp.async.commit_group;");
        }
        // next tile: second static tile known locally; afterwards work-steal
        // the 165 remainder tiles (atomics rare and time-staggered).
        if (!first && role == 0 && l == 0)
            tsl[p] = NSTAT + atomicAdd(&g_qctr, 1u);
        asm volatile("cp.async.wait_group 0;");
        barp(bid);                                     // staged + tsl visible
        unsigned tn = first ? (t + 1u) : tsl[p];

        // ---- packed per-lane sumsq of own entity row (full 32 chunks) ----
        ull q0 = 0ull, q1 = 0ull;
        #pragma unroll
        for (int i = 0; i < 32; i += 2) {
            ulonglong2 a = myrow2[i];
            ulonglong2 b = myrow2[i + 1];
            q0 = fma2(a.x, a.x, q0);
            q1 = fma2(a.y, a.y, q1);
            q0 = fma2(b.x, b.x, q0);
            q1 = fma2(b.y, b.y, q1);
        }
        float2 qf = upk(add2(q0, q1));
        float inv = -rsqrtf(fmaxf(qf.x + qf.y, 1e-24f));   // xn = -x/||x||
        ull nI = pk2(inv, inv);

        ull acc[8];
        #pragma unroll
        for (int j = 0; j < 8; j++) acc[j] = 0ull;

        // 8 groups of 4 chunks: batch x, prescale (mul2, rt2), then 2-operand math
        #pragma unroll 4
        for (int g = 0; g < 8; g++) {
            ull xn[8];
            #pragma unroll
            for (int q = 0; q < 4; q++) {
                ulonglong2 xx = myrow2[g * 4 + q];     // immediate offsets
                xn[2*q]   = mul2(xx.x, nI);
                xn[2*q+1] = mul2(xx.y, nI);
            }
            #pragma unroll
            for (int q = 0; q < 4; q++) {
                int c = g * 4 + q;
                #pragma unroll
                for (int j = 0; j < 8; j++) {
                    ulonglong2 hh = hb[j * 32 + c];    // uniform -> broadcast, imm offs
                    acc[j] = add2(acc[j], abs2(add2(xn[2*q],   hh.x)));
                    acc[j] = add2(acc[j], abs2(add2(xn[2*q+1], hh.y)));
                }
            }
        }

        // exp + store (dist <= ~34: no max pass), coalesced per b
        {
            float* outp = out + (size_t)bq * NENT + base + l;
            #pragma unroll
            for (int j = 0; j < 8; j++) {
                float2 f = upk(acc[j]);
                float e = __expf(f.x + f.y);
                outp[(size_t)j * NENT] = e;
                es[j] += e;
            }
        }

        barp(bid);                                     // pair done reading staging
        t = tn;
    }

    // ---- warp -> block row sums ----
    #pragma unroll
    for (int j = 0; j < 8; j++) {
        float s = wsum(es[j]);
        if (l == 0) sp[w][j] = s;
    }
    __syncthreads();
    if (tid < NB) {
        int b = tid, rr = b >> 3, j = b & 7;
        float s = 0.f;
        #pragma unroll
        for (int k = 0; k < NPAIR; k++) s += sp[2 * k + rr][j];
        g_part[b * GRID + blockIdx.x] = s;
    }

    // =============== grid-wide barrier (all 296 blocks co-resident) ===============
    __syncthreads();
    if (tid == 0) {
        __threadfence();
        unsigned old = atomicAdd(&g_done, 1u);
        unsigned target = (old / GRID + 1u) * GRID;
        if (old % GRID == GRID - 1u) g_qctr = 0u;      // reset queue for next replay
        unsigned d;
        do {
            asm volatile("ld.global.acquire.gpu.u32 %0, [%1];" : "=r"(d) : "l"(&g_done));
        } while (d < target);
    }
    __syncthreads();

    // ---- reduce partials -> 1/sum per row ----
    for (int b = w; b < NB; b += NW) {
        float s = 0.f;
        for (int i = l; i < GRID; i += 32) s += g_part[b * GRID + i];
        s = wsum(s);
        if (l == 0) sinv_s[b] = 1.0f / s;
    }
    __syncthreads();

    // =============== phase 2: normalize in place (L2-hot) ===============
    {
        const int total4 = NB * NENT / 4;              // 400000
        const int chunk  = (total4 + GRID - 1) / GRID; // 1352
        int start = blockIdx.x * chunk;
        int end   = min(start + chunk, total4);
        float4* o4 = (float4*)out;
        for (int i = start + tid; i < end; i += TPB) {
            int b = i / (NENT / 4);
            float iv = sinv_s[b];
            float4 v = o4[i];
            v.x *= iv; v.y *= iv; v.z *= iv; v.w *= iv;
            o4[i] = v;
        }
    }
}

// ---------------- launch ----------------
extern "C" void kernel_launch(void* const* d_in, const int* in_sizes, int n_in,
                              void* d_out, int out_size) {
    const int*   e1     = (const int*)d_in[0];
    const int*   rel    = (const int*)d_in[1];
    // d_in[2]=X, d_in[3]=A unused by the forward pass
    const float* ent    = (const float*)d_in[4];
    const float* relemb = (const float*)d_in[5];
    float* out = (float*)d_out;

    cudaFuncSetAttribute(k_fused, cudaFuncAttributeMaxDynamicSharedMemorySize, SMEM_BYTES);
    k_fused<<<GRID, TPB, SMEM_BYTES>>>(ent, relemb, e1, rel, out);
    (void)in_sizes; (void)n_in; (void)out_size;
}

// round 17
// speedup vs baseline: 1.0009x; 1.0009x over previous
#include <cuda_runtime.h>
#include <cstdint>

typedef unsigned long long ull;

#define NB      16
#define NENT    100000
#define NTILES  3125           // NENT / 32
#define GRID    296            // 2 blocks per SM (148 SMs)
#define TPB     192            // 6 warps = 3 pairs
#define NW      6
#define NPAIR   3
#define NPTOT   (GRID * NPAIR) // 888 pairs; pair gp owns tiles gp + k*888
#define RAW_F4  1024           // 16 KB raw landing buffer (row-major 32x512B)
#define PKD_F4  (32 * 33)      // pad-33 packed buffer (16.9 KB)
#define PAIR_F4 (RAW_F4 + PKD_F4)
#define TILE_BYTES 16384
// dynamic smem: h 512 f4 + 3 pairs * 2080 f4 = 6752 f4 = 108032 B (x2 blocks OK)
#define SMEM_BYTES ((512 + NPAIR * PAIR_F4) * 16)

// ---------------- device scratch (allocation-free) ----------------
__device__ float    g_part[NB * GRID];
__device__ unsigned g_done;    // grid barrier epoch counter (monotonic)

// ---------------- packed f32x2 helpers (sm_103a) ----------------
__device__ __forceinline__ ull add2(ull a, ull b) {
    ull r; asm("add.rn.f32x2 %0,%1,%2;" : "=l"(r) : "l"(a), "l"(b)); return r;
}
__device__ __forceinline__ ull fma2(ull a, ull b, ull c) {
    ull r; asm("fma.rn.f32x2 %0,%1,%2,%3;" : "=l"(r) : "l"(a), "l"(b), "l"(c)); return r;
}
__device__ __forceinline__ ull abs2(ull a) { return a & 0x7FFFFFFF7FFFFFFFull; }
__device__ __forceinline__ ull pk2(float a, float b) {
    ull r; asm("mov.b64 %0,{%1,%2};" : "=l"(r) : "f"(a), "f"(b)); return r;
}
__device__ __forceinline__ float2 upk(ull a) {
    float2 f; asm("mov.b64 {%0,%1},%2;" : "=f"(f.x), "=f"(f.y) : "l"(a)); return f;
}
__device__ __forceinline__ float wsum(float v) {
    #pragma unroll
    for (int o = 16; o; o >>= 1) v += __shfl_xor_sync(0xffffffffu, v, o);
    return v;
}
__device__ __forceinline__ unsigned sm_u32(const void* p) {
    unsigned a;
    asm("{ .reg .u64 t; cvta.to.shared.u64 t, %1; cvt.u32.u64 %0, t; }" : "=r"(a) : "l"(p));
    return a;
}
__device__ __forceinline__ void barp(int id) {   // pair barrier: 64 threads
    asm volatile("bar.sync %0, 64;" :: "r"(id) : "memory");
}
__device__ __forceinline__ void mbar_init(unsigned mbar, unsigned cnt) {
    asm volatile("mbarrier.init.shared.b64 [%0], %1;" :: "r"(mbar), "r"(cnt) : "memory");
}
__device__ __forceinline__ void mbar_expect_tx(unsigned mbar, unsigned bytes) {
    asm volatile("mbarrier.arrive.expect_tx.shared.b64 _, [%0], %1;"
                 :: "r"(mbar), "r"(bytes) : "memory");
}
__device__ __forceinline__ void bulk_g2s(unsigned dst, const void* src,
                                         unsigned bytes, unsigned mbar) {
    asm volatile("cp.async.bulk.shared::cta.global.mbarrier::complete_tx::bytes "
                 "[%0], [%1], %2, [%3];"
                 :: "r"(dst), "l"(src), "r"(bytes), "r"(mbar) : "memory");
}
__device__ __forceinline__ void mbar_wait(unsigned mbar, unsigned parity) {
    asm volatile(
        "{\n\t.reg .pred P1;\n"
        "W_%=:\n\t"
        "mbarrier.try_wait.parity.acquire.cta.shared::cta.b64 P1, [%0], %1, 0x989680;\n\t"
        "@P1 bra.uni D_%=;\n\t"
        "bra.uni W_%=;\n"
        "D_%=:\n\t}"
        :: "r"(mbar), "r"(parity) : "memory");
}

// =============== single fused kernel ===============
__global__ void __launch_bounds__(TPB, 2)
k_fused(const float* __restrict__ ent, const float* __restrict__ relemb,
        const int* __restrict__ e1w, const int* __restrict__ relw,
        float* __restrict__ out) {
    extern __shared__ float smf[];
    float*      hs  = smf;                             // 16*128 floats, persistent
    ulonglong2* hs2 = (ulonglong2*)smf;                // [16][32] 16B chunks
    float4*     sm4 = (float4*)smf;

    int tid = threadIdx.x, w = tid >> 5, l = tid & 31;
    int p = w >> 1, role = w & 1;                      // pair id, b-half role

    float4* raw4 = sm4 + 512 + p * PAIR_F4;            // 32 rows x 32 f4 (row-major)
    float4* pkd4 = raw4 + RAW_F4;                      // 32 rows x 33 f4 (pad-33)
    unsigned raw_u = sm_u32(raw4);
    const ulonglong2* myrow2 = (const ulonglong2*)(pkd4 + l * 33);

    __shared__ ull   mbar_sh[NPAIR];
    __shared__ float sp[NW][8];
    __shared__ float sinv_s[NB];
    unsigned mb_u = sm_u32(&mbar_sh[p]);

    // ---- mbarrier init BEFORE any TMA ----
    if (tid < NPAIR) mbar_init(sm_u32(&mbar_sh[tid]), 1u);
    __syncthreads();

    // ---- static schedule: pair gp owns gp + k*888 ----
    const unsigned gp = (unsigned)blockIdx.x * NPAIR + (unsigned)p;  // 0..887
    unsigned t = gp;

    // ---- prologue: launch tile gp's bulk copy (overlaps h-build) ----
    if (role == 0 && l == 0) {
        mbar_expect_tx(mb_u, TILE_BYTES);
        bulk_g2s(raw_u, (const char*)ent + (size_t)t * TILE_BYTES, TILE_BYTES, mb_u);
    }

    // ---- index width detection (int64 => high words zero) ----
    int odd  = e1w[1] | e1w[3] | e1w[5] | e1w[7] | e1w[9] | e1w[11] | e1w[13] | e1w[15];
    int is64 = (odd == 0);

    // ---- build h = norm(ent[e1[b]]) + norm(rel[rel[b]]) (covers the fetch) ----
    for (int b = w; b < NB; b += NW) {
        long long ei, ri;
        if (is64) { ei = ((const long long*)e1w)[b]; ri = ((const long long*)relw)[b]; }
        else      { ei = (long long)e1w[b];          ri = (long long)relw[b]; }
        float4 a = ((const float4*)ent)[(size_t)ei * 32 + l];
        float sa = wsum(fmaf(a.x, a.x, fmaf(a.y, a.y, fmaf(a.z, a.z, a.w * a.w))));
        float ia = rsqrtf(fmaxf(sa, 1e-24f));
        float4 c = ((const float4*)relemb)[(size_t)ri * 32 + l];
        float sc = wsum(fmaf(c.x, c.x, fmaf(c.y, c.y, fmaf(c.z, c.z, c.w * c.w))));
        float ic = rsqrtf(fmaxf(sc, 1e-24f));
        float4 h;
        h.x = fmaf(a.x, ia, c.x * ic);
        h.y = fmaf(a.y, ia, c.y * ic);
        h.z = fmaf(a.z, ia, c.z * ic);
        h.w = fmaf(a.w, ia, c.w * ic);
        ((float4*)hs)[b * 32 + l] = h;
    }
    __syncthreads();

    float es[8];
    #pragma unroll
    for (int j = 0; j < 8; j++) es[j] = 0.0f;
    const int bq  = role * 8;                          // my b rows: bq..bq+7
    const int bid = p + 1;                             // named barrier id
    const ulonglong2* hb = hs2 + bq * 32;

    unsigned ph = 0;

    // =============== phase 1: dist -> exp -> store ===============
    while (t < (unsigned)NTILES) {
        mbar_wait(mb_u, ph);                           // raw tile resident
        ph ^= 1u;

        // ---- repack raw (row-major) -> pkd (pad-33); both patterns conflict-free
        #pragma unroll
        for (int i = 0; i < 16; i++) {
            int row = role * 16 + i;
            float4 v = raw4[row * 32 + l];             // read granule l&7
            pkd4[row * 33 + l] = v;                    // write granule (row+l)&7
        }
        barp(bid);                                     // repack done: raw free

        // ---- issue next tile's bulk copy; math below covers the DRAM fetch ----
        unsigned tn = t + (unsigned)NPTOT;
        if (role == 0 && l == 0 && tn < (unsigned)NTILES) {
            mbar_expect_tx(mb_u, TILE_BYTES);
            bulk_g2s(raw_u, (const char*)ent + (size_t)tn * TILE_BYTES, TILE_BYTES, mb_u);
        }

        // ---- per-lane sumsq of own entity row (conflict-free, immediate offsets)
        const float4* myrow4 = pkd4 + l * 33;
        float s0 = 0.f, s1 = 0.f, s2 = 0.f, s3 = 0.f;
        #pragma unroll
        for (int c = 0; c < 32; c += 4) {
            float4 v0 = myrow4[c], v1 = myrow4[c+1], v2 = myrow4[c+2], v3 = myrow4[c+3];
            s0 = fmaf(v0.x, v0.x, fmaf(v0.y, v0.y, fmaf(v0.z, v0.z, fmaf(v0.w, v0.w, s0))));
            s1 = fmaf(v1.x, v1.x, fmaf(v1.y, v1.y, fmaf(v1.z, v1.z, fmaf(v1.w, v1.w, s1))));
            s2 = fmaf(v2.x, v2.x, fmaf(v2.y, v2.y, fmaf(v2.z, v2.z, fmaf(v2.w, v2.w, s2))));
            s3 = fmaf(v3.x, v3.x, fmaf(v3.y, v3.y, fmaf(v3.z, v3.z, fmaf(v3.w, v3.w, s3))));
        }
        float ss  = (s0 + s1) + (s2 + s3);
        float inv = -rsqrtf(fmaxf(ss, 1e-24f));        // diff = fma(x, -inv, h)
        ull nI = pk2(inv, inv);

        ull acc[8];
        #pragma unroll
        for (int j = 0; j < 8; j++) acc[j] = 0ull;

        // 8 groups of 4 chunks: batch x into registers, then pure math (R13 inner)
        #pragma unroll 4
        for (int g = 0; g < 8; g++) {
            ull xr[8];
            #pragma unroll
            for (int q = 0; q < 4; q++) {
                ulonglong2 xx = myrow2[g * 4 + q];     // immediate offsets
                xr[2*q]   = xx.x;
                xr[2*q+1] = xx.y;
            }
            #pragma unroll
            for (int q = 0; q < 4; q++) {
                int c = g * 4 + q;
                #pragma unroll
                for (int j = 0; j < 8; j++) {
                    ulonglong2 hh = hb[j * 32 + c];    // uniform -> broadcast
                    acc[j] = add2(acc[j], abs2(fma2(xr[2*q],   nI, hh.x)));
                    acc[j] = add2(acc[j], abs2(fma2(xr[2*q+1], nI, hh.y)));
                }
            }
        }

        // exp + store (dist <= ~34: no max pass), coalesced per b
        {
            float* outp = out + (size_t)bq * NENT + (size_t)t * 32 + l;
            #pragma unroll
            for (int j = 0; j < 8; j++) {
                float2 f = upk(acc[j]);
                float e = __expf(f.x + f.y);
                outp[(size_t)j * NENT] = e;
                es[j] += e;
            }
        }

        barp(bid);                                     // pair done reading pkd
        t = tn;
    }

    // ---- warp -> block row sums ----
    #pragma unroll
    for (int j = 0; j < 8; j++) {
        float s = wsum(es[j]);
        if (l == 0) sp[w][j] = s;
    }
    __syncthreads();
    if (tid < NB) {
        int b = tid, rr = b >> 3, j = b & 7;
        float s = 0.f;
        #pragma unroll
        for (int k = 0; k < NPAIR; k++) s += sp[2 * k + rr][j];
        g_part[b * GRID + blockIdx.x] = s;
    }

    // =============== grid-wide barrier (all 296 blocks co-resident) ===============
    __syncthreads();
    if (tid == 0) {
        __threadfence();
        unsigned old = atomicAdd(&g_done, 1u);
        unsigned target = (old / GRID + 1u) * GRID;
        unsigned d;
        do {
            asm volatile("ld.global.acquire.gpu.u32 %0, [%1];" : "=r"(d) : "l"(&g_done));
        } while (d < target);
    }
    __syncthreads();

    // ---- reduce partials -> 1/sum per row ----
    for (int b = w; b < NB; b += NW) {
        float s = 0.f;
        for (int i = l; i < GRID; i += 32) s += g_part[b * GRID + i];
        s = wsum(s);
        if (l == 0) sinv_s[b] = 1.0f / s;
    }
    __syncthreads();

    // =============== phase 2: normalize in place (L2-hot) ===============
    {
        const int total4 = NB * NENT / 4;              // 400000
        const int chunk  = (total4 + GRID - 1) / GRID; // 1352
        int start = blockIdx.x * chunk;
        int end   = min(start + chunk, total4);
        float4* o4 = (float4*)out;
        for (int i = start + tid; i < end; i += TPB) {
            int b = i / (NENT / 4);
            float iv = sinv_s[b];
            float4 v = o4[i];
            v.x *= iv; v.y *= iv; v.z *= iv; v.w *= iv;
            o4[i] = v;
        }
    }
}

// ---------------- launch ----------------
extern "C" void kernel_launch(void* const* d_in, const int* in_sizes, int n_in,
                              void* d_out, int out_size) {
    const int*   e1     = (const int*)d_in[0];
    const int*   rel    = (const int*)d_in[1];
    // d_in[2]=X, d_in[3]=A unused by the forward pass
    const float* ent    = (const float*)d_in[4];
    const float* relemb = (const float*)d_in[5];
    float* out = (float*)d_out;

    cudaFuncSetAttribute(k_fused, cudaFuncAttributeMaxDynamicSharedMemorySize, SMEM_BYTES);
    k_fused<<<GRID, TPB, SMEM_BYTES>>>(ent, relemb, e1, rel, out);
    (void)in_sizes; (void)n_in; (void)out_size;
}